// round 1
// baseline (speedup 1.0000x reference)
#include <cuda_runtime.h>
#include <math.h>

#define Bq   2
#define Nn   512
#define DIN  32
#define DHD  64
#define Hh   4
#define Cc   256
#define BN   (Bq*Nn)

__device__ float g_ne[Nn*DHD];
__device__ float g_mbias[Nn*Nn];
__device__ float g_xl[BN*Cc];
__device__ float g_xr[BN*Cc];
__device__ float g_al[Hh*BN];
__device__ float g_ar[Hh*BN];
__device__ float g_attout[BN*Cc];
__device__ float g_hln[BN*Cc];

__global__ void ne_kernel(const float* __restrict__ emb) {
    int i = blockIdx.x, t = threadIdx.x;
    float v = emb[i*DHD + t];
    float s = v*v;
    #pragma unroll
    for (int o = 16; o; o >>= 1) s += __shfl_xor_sync(0xffffffffu, s, o);
    __shared__ float sm[2];
    if ((t & 31) == 0) sm[t >> 5] = s;
    __syncthreads();
    float inv = rsqrtf(sm[0] + sm[1]);
    g_ne[i*DHD + t] = v * inv;
}

__global__ void __launch_bounds__(256) mask_kernel() {
    __shared__ float A_s[64][65];
    __shared__ float B_s[64][65];
    int i0 = blockIdx.y * 64, j0 = blockIdx.x * 64;
    int t = threadIdx.x, tx = t & 15, ty = t >> 4;

    #pragma unroll
    for (int p = 0; p < 16; p++) {
        int idx = t + p*256;
        int r = idx >> 6, d = idx & 63;
        A_s[r][d] = g_ne[(i0 + r)*DHD + d];
        B_s[r][d] = g_ne[(j0 + r)*DHD + d];
    }
    __syncthreads();

    float acc[4][4];
    #pragma unroll
    for (int r = 0; r < 4; r++)
        #pragma unroll
        for (int c = 0; c < 4; c++) acc[r][c] = 0.f;

    #pragma unroll
    for (int k = 0; k < 64; k++) {
        float a[4], bb[4];
        #pragma unroll
        for (int r = 0; r < 4; r++) a[r] = A_s[ty + 16*r][k];
        #pragma unroll
        for (int c = 0; c < 4; c++) bb[c] = B_s[tx + 16*c][k];
        #pragma unroll
        for (int r = 0; r < 4; r++)
            #pragma unroll
            for (int c = 0; c < 4; c++) acc[r][c] += a[r]*bb[c];
    }
    #pragma unroll
    for (int r = 0; r < 4; r++)
        #pragma unroll
        for (int c = 0; c < 4; c++) {
            int gi = i0 + ty + 16*r, gj = j0 + tx + 16*c;
            g_mbias[gi*Nn + gj] = (acc[r][c] != 0.0f || gi == gj) ? 0.0f : -1e30f;
        }
}

template<int K>
__global__ void __launch_bounds__(256) proj_kernel(
    const float* __restrict__ Xopt,
    const float* __restrict__ W,
    const float* __restrict__ bias,
    int dsel)
{
    const float* X = Xopt ? Xopt : g_hln;
    float* outp = dsel ? g_xr : g_xl;

    __shared__ float A_s[64][33];
    __shared__ float W_s[32][65];
    int m0 = blockIdx.y * 64, n0 = blockIdx.x * 64;
    int t = threadIdx.x, tx = t & 15, ty = t >> 4;

    float acc[4][4];
    #pragma unroll
    for (int r = 0; r < 4; r++)
        #pragma unroll
        for (int c = 0; c < 4; c++) acc[r][c] = 0.f;

    for (int kc = 0; kc < K; kc += 32) {
        __syncthreads();
        #pragma unroll
        for (int p = 0; p < 8; p++) {
            int row = (t >> 5) + p*8;
            int col = t & 31;
            A_s[row][col] = X[(m0 + row)*K + kc + col];
        }
        #pragma unroll
        for (int p = 0; p < 8; p++) {
            int kk  = (t >> 6) + p*4;
            int col = t & 63;
            W_s[kk][col] = W[(kc + kk)*Cc + n0 + col];
        }
        __syncthreads();
        #pragma unroll
        for (int kk = 0; kk < 32; kk++) {
            float a[4], bb[4];
            #pragma unroll
            for (int r = 0; r < 4; r++) a[r] = A_s[ty + 16*r][kk];
            #pragma unroll
            for (int c = 0; c < 4; c++) bb[c] = W_s[kk][tx + 16*c];
            #pragma unroll
            for (int r = 0; r < 4; r++)
                #pragma unroll
                for (int c = 0; c < 4; c++) acc[r][c] += a[r]*bb[c];
        }
    }
    #pragma unroll
    for (int r = 0; r < 4; r++)
        #pragma unroll
        for (int c = 0; c < 4; c++) {
            int n = n0 + tx + 16*c;
            outp[(m0 + ty + 16*r)*Cc + n] = acc[r][c] + bias[n];
        }
}

__global__ void av_kernel(const float* __restrict__ att) {
    int m = blockIdx.x;
    int t = threadIdx.x, w = t >> 5, l = t & 31, hh = w & 3;
    const float* src = (w < 4) ? g_xl : g_xr;
    float v = src[m*Cc + hh*64 + l]      * att[hh*64 + l]
            + src[m*Cc + hh*64 + 32 + l] * att[hh*64 + 32 + l];
    #pragma unroll
    for (int o = 16; o; o >>= 1) v += __shfl_xor_sync(0xffffffffu, v, o);
    if (l == 0) {
        float* dst = (w < 4) ? g_al : g_ar;
        dst[hh*BN + m] = 0.6f * v;
    }
}

__global__ void __launch_bounds__(256) attn_kernel(
    const float* __restrict__ att,
    const float* __restrict__ bias,
    float* __restrict__ outopt)
{
    float* out = outopt ? outopt : g_attout;
    const int b = blockIdx.z, h = blockIdx.y, i0 = blockIdx.x * 32;
    const int t = threadIdx.x, w = t >> 5, l = t & 31;

    __shared__ float xr_s[32][64];
    __shared__ float xl_s[64][68];
    __shared__ float p_s[32][64];
    __shared__ float batt_s[64];
    __shared__ float al_s[64];

    #pragma unroll
    for (int p = 0; p < 8; p++) {
        int idx = t + p*256;
        int r = idx >> 6, d = idx & 63;
        xr_s[r][d] = g_xr[(b*Nn + i0 + r)*Cc + h*64 + d];
    }
    if (t < 64) batt_s[t] = 0.4f * att[h*64 + t];
    __syncthreads();

    float arr[4];
    #pragma unroll
    for (int k = 0; k < 4; k++) arr[k] = g_ar[h*BN + b*Nn + i0 + w*4 + k];

    float m_run[4], l_run[4], acc0[4], acc1[4];
    #pragma unroll
    for (int k = 0; k < 4; k++) { m_run[k] = -3.0e38f; l_run[k] = 0.f; acc0[k] = 0.f; acc1[k] = 0.f; }

    for (int c = 0; c < 8; c++) {
        const int j0 = c * 64;
        __syncthreads();
        #pragma unroll
        for (int p = 0; p < 16; p++) {
            int idx = t + p*256;
            int jj = idx >> 6, d = idx & 63;
            xl_s[jj][d] = g_xl[(b*Nn + j0 + jj)*Cc + h*64 + d];
        }
        if (t < 64) al_s[t] = g_al[h*BN + b*Nn + j0 + t];
        __syncthreads();

        float2 mb[4];
        #pragma unroll
        for (int k = 0; k < 4; k++)
            mb[k] = *reinterpret_cast<const float2*>(&g_mbias[(i0 + w*4 + k)*Nn + j0 + 2*l]);

        float s0[4], s1[4];
        #pragma unroll
        for (int k = 0; k < 4; k++) { s0[k] = 0.f; s1[k] = 0.f; }

        const float4* xlp0 = reinterpret_cast<const float4*>(&xl_s[2*l][0]);
        const float4* xlp1 = reinterpret_cast<const float4*>(&xl_s[2*l + 1][0]);
        const float4* bt4  = reinterpret_cast<const float4*>(batt_s);
        #pragma unroll
        for (int q = 0; q < 16; q++) {
            float4 bt = bt4[q];
            float4 a0 = xlp0[q];
            float4 a1 = xlp1[q];
            #pragma unroll
            for (int k = 0; k < 4; k++) {
                float4 rr = *reinterpret_cast<const float4*>(&xr_s[w*4 + k][q*4]);
                s0[k] += bt.x * fabsf(rr.x + a0.x);
                s0[k] += bt.y * fabsf(rr.y + a0.y);
                s0[k] += bt.z * fabsf(rr.z + a0.z);
                s0[k] += bt.w * fabsf(rr.w + a0.w);
                s1[k] += bt.x * fabsf(rr.x + a1.x);
                s1[k] += bt.y * fabsf(rr.y + a1.y);
                s1[k] += bt.z * fabsf(rr.z + a1.z);
                s1[k] += bt.w * fabsf(rr.w + a1.w);
            }
        }
        float alj0 = al_s[2*l], alj1 = al_s[2*l + 1];
        #pragma unroll
        for (int k = 0; k < 4; k++) {
            s0[k] += arr[k] + alj0 + mb[k].x;
            s1[k] += arr[k] + alj1 + mb[k].y;
        }

        #pragma unroll
        for (int k = 0; k < 4; k++) {
            float mloc = fmaxf(s0[k], s1[k]);
            #pragma unroll
            for (int o = 16; o; o >>= 1) mloc = fmaxf(mloc, __shfl_xor_sync(0xffffffffu, mloc, o));
            float mnew = fmaxf(m_run[k], mloc);
            float corr = __expf(m_run[k] - mnew);
            m_run[k] = mnew;
            float p0 = __expf(s0[k] - mnew);
            float p1 = __expf(s1[k] - mnew);
            *reinterpret_cast<float2*>(&p_s[w*4 + k][2*l]) = make_float2(p0, p1);
            float ps = p0 + p1;
            #pragma unroll
            for (int o = 16; o; o >>= 1) ps += __shfl_xor_sync(0xffffffffu, ps, o);
            l_run[k] = l_run[k]*corr + ps;
            acc0[k] *= corr;
            acc1[k] *= corr;
        }
        __syncwarp();

        #pragma unroll 8
        for (int jj = 0; jj < 64; jj++) {
            float2 xv = *reinterpret_cast<const float2*>(&xl_s[jj][2*l]);
            #pragma unroll
            for (int k = 0; k < 4; k++) {
                float pk = p_s[w*4 + k][jj];
                acc0[k] += pk * xv.x;
                acc1[k] += pk * xv.y;
            }
        }
    }

    float2 bv = *reinterpret_cast<const float2*>(&bias[h*64 + 2*l]);
    #pragma unroll
    for (int k = 0; k < 4; k++) {
        float inv = 1.0f / l_run[k];
        int i = i0 + w*4 + k;
        float2 o = make_float2(acc0[k]*inv + bv.x, acc1[k]*inv + bv.y);
        *reinterpret_cast<float2*>(&out[(b*Nn + i)*Cc + h*64 + 2*l]) = o;
    }
}

__device__ __forceinline__ float block_sum256(float v) {
    #pragma unroll
    for (int o = 16; o; o >>= 1) v += __shfl_xor_sync(0xffffffffu, v, o);
    __shared__ float red[8];
    int w = threadIdx.x >> 5;
    if ((threadIdx.x & 31) == 0) red[w] = v;
    __syncthreads();
    v = red[0]+red[1]+red[2]+red[3]+red[4]+red[5]+red[6]+red[7];
    __syncthreads();
    return v;
}

__global__ void ln_kernel(const float* __restrict__ g,
                          const float* __restrict__ be,
                          float* __restrict__ outopt,
                          int do_relu)
{
    float* out = outopt ? outopt : g_hln;
    int m = blockIdx.x, t = threadIdx.x;
    float v = g_attout[m*Cc + t];
    float mu = block_sum256(v) * (1.0f/Cc);
    float d = v - mu;
    float var = block_sum256(d*d) * (1.0f/Cc);
    float o = d * rsqrtf(var + 1e-5f) * g[t] + be[t];
    if (do_relu) o = fmaxf(o, 0.0f);
    out[m*Cc + t] = o;
}

extern "C" void kernel_launch(void* const* d_in, const int* in_sizes, int n_in,
                              void* d_out, int out_size) {
    const float* x     = (const float*)d_in[0];
    const float* emb   = (const float*)d_in[1];
    const float* w1l   = (const float*)d_in[2];
    const float* b1l   = (const float*)d_in[3];
    const float* w1r   = (const float*)d_in[4];
    const float* b1r   = (const float*)d_in[5];
    const float* att1  = (const float*)d_in[6];
    const float* bias1 = (const float*)d_in[7];
    const float* g1    = (const float*)d_in[8];
    const float* be1   = (const float*)d_in[9];
    const float* w2l   = (const float*)d_in[10];
    const float* b2l   = (const float*)d_in[11];
    const float* w2r   = (const float*)d_in[12];
    const float* b2r   = (const float*)d_in[13];
    const float* att2  = (const float*)d_in[14];
    const float* bias2 = (const float*)d_in[15];
    const float* g2    = (const float*)d_in[16];
    const float* be2   = (const float*)d_in[17];
    float* out = (float*)d_out;

    ne_kernel<<<Nn, DHD>>>(emb);
    mask_kernel<<<dim3(8, 8), 256>>>();

    proj_kernel<DIN><<<dim3(4, 16), 256>>>(x, w1l, b1l, 0);
    proj_kernel<DIN><<<dim3(4, 16), 256>>>(x, w1r, b1r, 1);
    av_kernel<<<BN, 256>>>(att1);
    attn_kernel<<<dim3(16, 4, 2), 256>>>(att1, bias1, nullptr);
    ln_kernel<<<BN, 256>>>(g1, be1, nullptr, 1);

    proj_kernel<Cc><<<dim3(4, 16), 256>>>(nullptr, w2l, b2l, 0);
    proj_kernel<Cc><<<dim3(4, 16), 256>>>(nullptr, w2r, b2r, 1);
    av_kernel<<<BN, 256>>>(att2);
    attn_kernel<<<dim3(16, 4, 2), 256>>>(att2, bias2, nullptr);
    ln_kernel<<<BN, 256>>>(g2, be2, out, 0);
}